// round 7
// baseline (speedup 1.0000x reference)
#include <cuda_runtime.h>
#include <cuda_fp16.h>
#include <math.h>
#include <stdint.h>

// Shapes (fixed)
#define HW_DIM  1024
#define C_DIM   256
#define N_TOK   32768
#define K_CODES 1024
#define Z_ELEMS 8388608
#define BETA_F  0.25f
#define MARGIN  0.75f

// phase1 tiling: CTA = 256 tokens x 1024 codes; 16 pairs x (2 x 32-code chunks)
#define MT      256
#define NCTA    (N_TOK / MT)     // 128 CTAs -> single wave
#define PAIRS   16
#define KSTEPS  16

// phase1 smem (bytes)
#define ROWB    528              // 264 halves per row (528%128=16 -> ldsm clean)
#define A_OFF   0                // 256*528 = 135168
#define RING_OFF 135168          // 4 slots x 16896
#define RSLOT   16896
#define NS_OFF  202752           // 1024 floats
#define CV_OFF  206848           // 256*2 floats
#define CI_OFF  208896           // 256*2 ints
#define C2_OFF  210944           // 256*2 floats
#define KF_OFF  212992           // 256 ints
#define SMEM1   214016

static __device__ int      g_counts[K_CODES];
static __device__ float    g_norms[K_CODES];
static __device__ float    g_partials[NCTA];
static __device__ float    g_partials2[128];
static __device__ unsigned g_flag[N_TOK / 32];       // 1024 words
static __device__ __half   g_cb16[K_CODES * 264];    // fp16 codebook, padded rows

// ---------------------------------------------------------------------------
__device__ __forceinline__ uint32_t smem_u32(const void* p) {
    uint32_t a;
    asm("{ .reg .u64 T; cvta.to.shared.u64 T, %1; cvt.u32.u64 %0, T; }"
        : "=r"(a) : "l"(p));
    return a;
}
__device__ __forceinline__ void ldsm4(uint32_t addr, uint32_t r[4]) {
    asm volatile("ldmatrix.sync.aligned.m8n8.x4.shared.b16 {%0,%1,%2,%3}, [%4];"
                 : "=r"(r[0]), "=r"(r[1]), "=r"(r[2]), "=r"(r[3]) : "r"(addr));
}
__device__ __forceinline__ void mma_f16(float c[4], const uint32_t a[4],
                                        uint32_t b0, uint32_t b1) {
    asm volatile(
        "mma.sync.aligned.m16n8k16.row.col.f32.f16.f16.f32 "
        "{%0,%1,%2,%3}, {%4,%5,%6,%7}, {%8,%9}, {%0,%1,%2,%3};"
        : "+f"(c[0]), "+f"(c[1]), "+f"(c[2]), "+f"(c[3])
        : "r"(a[0]), "r"(a[1]), "r"(a[2]), "r"(a[3]), "r"(b0), "r"(b1));
}
#define CP_ASYNC16(dst, src) \
    asm volatile("cp.async.cg.shared.global [%0], [%1], 16;" :: "r"(dst), "l"(src))
#define CP_COMMIT() asm volatile("cp.async.commit_group;" ::: "memory")
#define CP_WAIT2()  asm volatile("cp.async.wait_group 2;" ::: "memory")
#define CP_WAIT0()  asm volatile("cp.async.wait_group 0;" ::: "memory")

// ---------------------------------------------------------------------------
// prep: fp16 codebook + norms + zero counts/flags/partials2
__global__ void prep_kernel(const float* __restrict__ cb) {
    __shared__ float red[8];
    const int code = blockIdx.x;
    const int c    = threadIdx.x;
    float v = cb[code * C_DIM + c];
    g_cb16[code * 264 + c] = __float2half_rn(v);
    if (c < 8) g_cb16[code * 264 + 256 + c] = __float2half_rn(0.f);
    float s = v * v;
    #pragma unroll
    for (int off = 16; off > 0; off >>= 1)
        s += __shfl_down_sync(0xffffffffu, s, off);
    if ((c & 31) == 0) red[c >> 5] = s;
    __syncthreads();
    if (c == 0) {
        float t = 0.f;
        #pragma unroll
        for (int i = 0; i < 8; i++) t += red[i];
        g_norms[code]  = t;
        g_counts[code] = 0;
        g_flag[code]   = 0u;              // 1024 words == gridDim
    }
    if (code < 128 && c == 1) g_partials2[code] = 0.f;
}

// ---------------------------------------------------------------------------
// phase 1: fp16 coarse GEMM-argmin + margin flag + fused gather for confident.
// 8 warps = 4 token-groups(64 tok) x 2 chunk-halves; warp tile 64 tok x 32 codes.
__global__ __launch_bounds__(256, 1)
void phase1_kernel(const float* __restrict__ z, const float* __restrict__ cb,
                   float* __restrict__ out) {
    extern __shared__ char smem[];
    const uint32_t sb = smem_u32(smem);
    float* ns    = (float*)(smem + NS_OFF);
    float* candv = (float*)(smem + CV_OFF);
    int*   candi = (int*)(smem + CI_OFF);
    float* cand2 = (float*)(smem + C2_OFF);
    int*   kf    = (int*)(smem + KF_OFF);

    const int tid  = threadIdx.x;
    const int warp = tid >> 5;
    const int lane = tid & 31;
    const int tg   = warp & 3;
    const int cg   = warp >> 2;
    const int g    = lane >> 2;
    const int t    = lane & 3;

    const int n0  = blockIdx.x * MT;
    const int b   = n0 >> 10;
    const int hw0 = n0 & 1023;
    const float* zb = z + (size_t)b * (C_DIM * HW_DIM) + hw0;

    // chunk = 32 codes = 16896 contiguous bytes in g_cb16 -> linear copy
    auto prefetch = [&](int ch) {
        const char* src = (const char*)g_cb16 + (size_t)ch * RSLOT;
        uint32_t dst = sb + RING_OFF + (uint32_t)((ch & 3) * RSLOT);
        #pragma unroll
        for (int it = 0; it < 5; it++) {
            int i = it * 256 + tid;
            if (i < RSLOT / 16) CP_ASYNC16(dst + i * 16, src + i * 16);
        }
    };
    prefetch(0); CP_COMMIT();
    prefetch(1); CP_COMMIT();
    prefetch(2); CP_COMMIT();
    prefetch(3); CP_COMMIT();

    // stage A: 256 tok x 256 c as fp16, coalesced over tokens
    for (int it = 0; it < 256; it++) {
        int i  = it * 256 + tid;
        int tk = i & 255;
        int c  = i >> 8;
        *(__half*)(smem + A_OFF + tk * ROWB + c * 2) =
            __float2half_rn(zb[(size_t)c * HW_DIM + tk]);
    }
    #pragma unroll
    for (int it = 0; it < 4; it++) ns[it * 256 + tid] = g_norms[it * 256 + tid];

    const uint32_t aB = sb + A_OFF
        + (uint32_t)((tg * 64 + (lane & 15)) * ROWB + (lane >> 4) * 16);
    const uint32_t bOff = (uint32_t)((lane & 15) * ROWB + (lane >> 4) * 16);

    // 8 slots per thread: mt(4) x rowhalf(2); triple (v1, i1, v2)
    float v1[8], v2[8];
    int   i1[8];
    #pragma unroll
    for (int s = 0; s < 8; s++) { v1[s] = 3.4e38f; v2[s] = 3.4e38f; i1[s] = 0; }

    for (int p = 0; p < PAIRS; p++) {
        if (p == PAIRS - 1) CP_WAIT0(); else CP_WAIT2();
        __syncthreads();

        const uint32_t bBase = sb + RING_OFF
            + (uint32_t)(((2 * p + cg) & 3) * RSLOT) + bOff;

        float acc[4][4][4];
        #pragma unroll
        for (int mt = 0; mt < 4; mt++)
            #pragma unroll
            for (int nb = 0; nb < 4; nb++)
                #pragma unroll
                for (int q = 0; q < 4; q++) acc[mt][nb][q] = 0.f;

        #pragma unroll 4
        for (int ks = 0; ks < KSTEPS; ks++) {
            uint32_t ah[4][4], bb0[4], bb1[4];
            ldsm4(bBase + (uint32_t)(ks * 32), bb0);             // codes 0-15
            ldsm4(bBase + (uint32_t)(16 * ROWB + ks * 32), bb1); // codes 16-31
            #pragma unroll
            for (int mt = 0; mt < 4; mt++)
                ldsm4(aB + (uint32_t)(mt * 16 * ROWB + ks * 32), ah[mt]);
            #pragma unroll
            for (int nb = 0; nb < 4; nb++) {
                uint32_t b0 = (nb < 2) ? bb0[nb & 1]     : bb1[nb & 1];
                uint32_t b1 = (nb < 2) ? bb0[(nb & 1)+2] : bb1[(nb & 1)+2];
                #pragma unroll
                for (int mt = 0; mt < 4; mt++)
                    mma_f16(acc[mt][nb], ah[mt], b0, b1);
            }
        }

        __syncthreads();          // reads done before slots are refilled
        if (p < PAIRS - 2) {
            prefetch(2 * p + 4); CP_COMMIT();
            prefetch(2 * p + 5); CP_COMMIT();
        }

        // epilogue (regs only) overlaps the async loads
        #pragma unroll
        for (int nb = 0; nb < 4; nb++) {
            int cl = cg * 32 + nb * 8 + 2 * t;
            int code0 = p * 64 + cl;
            float nk0 = ns[code0];
            float nk1 = ns[code0 + 1];
            #pragma unroll
            for (int mt = 0; mt < 4; mt++) {
                #pragma unroll
                for (int h = 0; h < 2; h++) {
                    int s = mt * 2 + h;
                    float d0 = nk0 - 2.f * acc[mt][nb][h * 2];
                    float d1 = nk1 - 2.f * acc[mt][nb][h * 2 + 1];
                    if (d0 < v1[s]) { v2[s] = v1[s]; v1[s] = d0; i1[s] = code0; }
                    else if (d0 < v2[s]) v2[s] = d0;
                    if (d1 < v1[s]) { v2[s] = v1[s]; v1[s] = d1; i1[s] = code0 + 1; }
                    else if (d1 < v2[s]) v2[s] = d1;
                }
            }
        }
    }

    // lane reduce over t (lanes 4g..4g+3 share token rows): merge triples
    #pragma unroll
    for (int s = 0; s < 8; s++) {
        #pragma unroll
        for (int m = 1; m <= 2; m <<= 1) {
            float ov1 = __shfl_xor_sync(0xffffffffu, v1[s], m);
            int   oi1 = __shfl_xor_sync(0xffffffffu, i1[s], m);
            float ov2 = __shfl_xor_sync(0xffffffffu, v2[s], m);
            if (ov1 < v1[s] || (ov1 == v1[s] && oi1 < i1[s])) {
                v2[s] = fminf(v1[s], ov2); v1[s] = ov1; i1[s] = oi1;
            } else {
                v2[s] = fminf(v2[s], ov1);
            }
        }
    }
    if (t == 0) {
        #pragma unroll
        for (int s = 0; s < 8; s++) {
            int mt = s >> 1, h = s & 1;
            int tok = tg * 64 + mt * 16 + h * 8 + g;
            candv[tok * 2 + cg] = v1[s];
            candi[tok * 2 + cg] = i1[s];
            cand2[tok * 2 + cg] = v2[s];
        }
    }
    __syncthreads();

    if (tid < MT) {
        float a1 = candv[tid * 2],     b1v = candv[tid * 2 + 1];
        int   ai = candi[tid * 2],     bi  = candi[tid * 2 + 1];
        float a2 = cand2[tid * 2],     b2  = cand2[tid * 2 + 1];
        float V1, V2; int I1;
        if (b1v < a1 || (b1v == a1 && bi < ai)) {
            V1 = b1v; I1 = bi; V2 = fminf(a1, b2);
        } else {
            V1 = a1; I1 = ai; V2 = fminf(a2, b1v);
        }
        if (V2 - V1 >= MARGIN) {
            kf[tid] = I1;
            atomicAdd(&g_counts[I1], 1);
        } else {
            kf[tid] = -1;
            int tk = n0 + tid;
            atomicOr(&g_flag[tk >> 5], 1u << (tk & 31));
        }
    }
    __syncthreads();

    // fused gather + loss for confident tokens (thread per token)
    {
        const int k = kf[tid];
        float s = 0.f;
        if (k >= 0) {
            const float4* crow = (const float4*)(cb + (size_t)k * C_DIM);
            const float* zp = zb + tid;
            float* op = out + (size_t)b * (C_DIM * HW_DIM) + hw0 + tid;
            #pragma unroll 8
            for (int j = 0; j < 64; j++) {
                float4 e = crow[j];
                int c = j * 4;
                float d0 = e.x - zp[(c + 0) * HW_DIM];
                float d1 = e.y - zp[(c + 1) * HW_DIM];
                float d2 = e.z - zp[(c + 2) * HW_DIM];
                float d3 = e.w - zp[(c + 3) * HW_DIM];
                s += d0 * d0 + d1 * d1 + d2 * d2 + d3 * d3;
                op[(c + 0) * HW_DIM] = e.x;
                op[(c + 1) * HW_DIM] = e.y;
                op[(c + 2) * HW_DIM] = e.z;
                op[(c + 3) * HW_DIM] = e.w;
            }
        }
        float* red = candv;      // reuse (256 floats)
        red[tid] = s;
        __syncthreads();
        for (int off = 128; off > 0; off >>= 1) {
            if (tid < off) red[tid] += red[tid + off];
            __syncthreads();
        }
        if (tid == 0) g_partials[blockIdx.x] = red[0];
    }
}

// ---------------------------------------------------------------------------
// phase 2: exact fp32 argmin + gather + loss for flagged tokens.
// 128 blocks; block b owns token range [b*256, b*256+256). Deterministic.
__global__ __launch_bounds__(256)
void phase2_kernel(const float* __restrict__ z, const float* __restrict__ cb,
                   float* __restrict__ out) {
    __shared__ int   list[256];
    __shared__ int   wcnt[8];
    __shared__ float zs[8 * 260];
    __shared__ float cbs[32 * 260];
    __shared__ float wsum[8];

    const int tid  = threadIdx.x;
    const int warp = tid >> 5;
    const int lane = tid & 31;
    const int t0   = blockIdx.x * 256;

    // ordered flagged list
    int tok = t0 + tid;
    bool fl = (g_flag[tok >> 5] >> (tok & 31)) & 1u;
    unsigned bal = __ballot_sync(0xffffffffu, fl);
    int wpre = __popc(bal & ((1u << lane) - 1u));
    if (lane == 0) wcnt[warp] = __popc(bal);
    __syncthreads();
    int base = 0, nloc = 0;
    #pragma unroll
    for (int w = 0; w < 8; w++) { if (w < warp) base += wcnt[w]; nloc += wcnt[w]; }
    if (fl) list[base + wpre] = tok;
    if (lane == 0) wsum[warp] = 0.f;
    __syncthreads();
    if (nloc == 0) return;     // g_partials2 pre-zeroed

    float wacc = 0.f;

    for (int g0 = 0; g0 < nloc; g0 += 8) {
        int myTok = (g0 + warp < nloc) ? list[g0 + warp] : -1;
        __syncthreads();       // zs/cbs free from previous group
        if (myTok >= 0) {
            int tb = myTok >> 10, thw = myTok & 1023;
            const float* zp = z + (size_t)tb * (C_DIM * HW_DIM) + thw;
            #pragma unroll
            for (int j = 0; j < 8; j++)
                zs[warp * 260 + lane + 32 * j] = zp[(size_t)(lane + 32 * j) * HW_DIM];
        }

        float bv = 3.4e38f;
        int   bi = 0;
        for (int ch = 0; ch < 32; ch++) {
            __syncthreads();
            #pragma unroll
            for (int it = 0; it < 32; it++) {
                int i = it * 256 + tid;
                int r = i >> 8, c = i & 255;
                cbs[r * 260 + c] = cb[(size_t)(ch * 32 + r) * C_DIM + c];
            }
            __syncthreads();
            if (myTok >= 0) {
                const float4* cr = (const float4*)(cbs + lane * 260);
                const float4* zr = (const float4*)(zs + warp * 260);
                float dot = 0.f;
                #pragma unroll 16
                for (int c4 = 0; c4 < 64; c4++) {
                    float4 e = cr[c4];
                    float4 zz = zr[c4];
                    dot += e.x * zz.x + e.y * zz.y + e.z * zz.z + e.w * zz.w;
                }
                int code = ch * 32 + lane;
                float d = g_norms[code] - 2.f * dot;
                if (d < bv || (d == bv && code < bi)) { bv = d; bi = code; }
            }
        }
        __syncthreads();

        if (myTok >= 0) {
            // warp butterfly argmin (all lanes converge)
            #pragma unroll
            for (int m = 16; m > 0; m >>= 1) {
                float ov = __shfl_xor_sync(0xffffffffu, bv, m);
                int   oi = __shfl_xor_sync(0xffffffffu, bi, m);
                if (ov < bv || (ov == bv && oi < bi)) { bv = ov; bi = oi; }
            }
            if (lane == 0) atomicAdd(&g_counts[bi], 1);

            // gather + loss for this token
            int tb = myTok >> 10, thw = myTok & 1023;
            const float* zp = z + (size_t)tb * (C_DIM * HW_DIM) + thw;
            float* op = out + (size_t)tb * (C_DIM * HW_DIM) + thw;
            const float4* crow = (const float4*)(cb + (size_t)bi * C_DIM);
            float ls = 0.f;
            #pragma unroll
            for (int jj = 0; jj < 2; jj++) {
                int c4 = lane + jj * 32;
                float4 e = crow[c4];
                int c = c4 * 4;
                float d0 = e.x - zp[(c + 0) * HW_DIM];
                float d1 = e.y - zp[(c + 1) * HW_DIM];
                float d2 = e.z - zp[(c + 2) * HW_DIM];
                float d3 = e.w - zp[(c + 3) * HW_DIM];
                ls += d0 * d0 + d1 * d1 + d2 * d2 + d3 * d3;
                op[(c + 0) * HW_DIM] = e.x;
                op[(c + 1) * HW_DIM] = e.y;
                op[(c + 2) * HW_DIM] = e.z;
                op[(c + 3) * HW_DIM] = e.w;
            }
            #pragma unroll
            for (int m = 16; m > 0; m >>= 1)
                ls += __shfl_xor_sync(0xffffffffu, ls, m);
            wacc += ls;           // same on all lanes; lane0 value used below
        }
    }

    if (lane == 0) wsum[warp] = wacc;
    __syncthreads();
    if (tid == 0) {
        float s = 0.f;
        #pragma unroll
        for (int w = 0; w < 8; w++) s += wsum[w];
        g_partials2[blockIdx.x] = s;
    }
}

// ---------------------------------------------------------------------------
__global__ void finalize_kernel(float* __restrict__ out, int out_size) {
    __shared__ float s1[1024];
    __shared__ float s2[1024];
    const int tid = threadIdx.x;
    float ls = (tid < 128) ? (g_partials[tid] + g_partials2[tid]) : 0.f;
    float p  = (float)g_counts[tid] * (1.0f / (float)N_TOK);
    float pc = fmaxf(p, 1e-10f);
    s1[tid] = ls;
    s2[tid] = pc * logf(pc);
    __syncthreads();
    for (int off = 512; off > 0; off >>= 1) {
        if (tid < off) { s1[tid] += s1[tid + off]; s2[tid] += s2[tid + off]; }
        __syncthreads();
    }
    if (tid == 0) {
        float mse = s1[0] * (1.0f / (float)Z_ELEMS);
        if (out_size >= Z_ELEMS + 1) out[Z_ELEMS]     = mse * (1.0f + BETA_F);
        if (out_size >= Z_ELEMS + 2) out[Z_ELEMS + 1] = expf(-s2[0]);
    }
}

// ---------------------------------------------------------------------------
extern "C" void kernel_launch(void* const* d_in, const int* in_sizes, int n_in,
                              void* d_out, int out_size) {
    const float* z  = (const float*)d_in[0];
    const float* cb = (const float*)d_in[1];
    float* out = (float*)d_out;

    cudaFuncSetAttribute(phase1_kernel,
                         cudaFuncAttributeMaxDynamicSharedMemorySize, SMEM1);

    prep_kernel<<<K_CODES, 256>>>(cb);
    phase1_kernel<<<NCTA, 256, SMEM1>>>(z, cb, out);
    phase2_kernel<<<128, 256>>>(z, cb, out);
    finalize_kernel<<<1, 1024>>>(out, out_size);
}

// round 8
// speedup vs baseline: 2.6430x; 2.6430x over previous
#include <cuda_runtime.h>
#include <cuda_fp16.h>
#include <math.h>
#include <stdint.h>

// Shapes (fixed)
#define HW_DIM  1024
#define C_DIM   256
#define N_TOK   32768
#define K_CODES 1024
#define Z_ELEMS 8388608
#define BETA_F  0.25f

// tiling: CTA = 128 tokens x 1024 codes; 16 chunk-pairs of 64 codes
#define MT      128
#define NCTA    (N_TOK / MT)     // 256
#define PAIRS   16
#define KSTEPS  16

// smem layout (bytes)
#define AROWB   528              // A rows: 264 halves (528%128=16, ldsm clean)
#define AH_OFF  0                // 128*528 = 67584
#define RING_OFF 67584           // 2 pair-buffers x 65536 (64 codes x 1024B, swizzled)
#define PAIRB   65536
#define NS_OFF  198656           // 1024 floats -> 202752
#define SMEM_TOTAL 202752
// post-mainloop scratch aliases the ring:
#define CV_OFF  RING_OFF                  // 256 floats
#define CI_OFF  (RING_OFF + 1024)         // 256 ints
#define KF_OFF  (RING_OFF + 2048)         // 128 ints

static __device__ int    g_counts[K_CODES];
static __device__ float  g_norms[K_CODES];
static __device__ float  g_partials[NCTA];
// pre-split codebook: row = 1024B = 32 k-blocks of [hi x8 | lo x8] halves
static __device__ __half g_cbi[K_CODES * 512];

// ---------------------------------------------------------------------------
__device__ __forceinline__ uint32_t smem_u32(const void* p) {
    uint32_t a;
    asm("{ .reg .u64 T; cvta.to.shared.u64 T, %1; cvt.u32.u64 %0, T; }"
        : "=r"(a) : "l"(p));
    return a;
}
__device__ __forceinline__ void ldsm4(uint32_t addr, uint32_t r[4]) {
    asm volatile("ldmatrix.sync.aligned.m8n8.x4.shared.b16 {%0,%1,%2,%3}, [%4];"
                 : "=r"(r[0]), "=r"(r[1]), "=r"(r[2]), "=r"(r[3]) : "r"(addr));
}
__device__ __forceinline__ void mma_f16(float c[4], const uint32_t a[4],
                                        uint32_t b0, uint32_t b1) {
    asm volatile(
        "mma.sync.aligned.m16n8k16.row.col.f32.f16.f16.f32 "
        "{%0,%1,%2,%3}, {%4,%5,%6,%7}, {%8,%9}, {%0,%1,%2,%3};"
        : "+f"(c[0]), "+f"(c[1]), "+f"(c[2]), "+f"(c[3])
        : "r"(a[0]), "r"(a[1]), "r"(a[2]), "r"(a[3]), "r"(b0), "r"(b1));
}
#define CP_ASYNC16(dst, src) \
    asm volatile("cp.async.cg.shared.global [%0], [%1], 16;" :: "r"(dst), "l"(src))
#define CP_COMMIT() asm volatile("cp.async.commit_group;" ::: "memory")
#define CP_WAIT1()  asm volatile("cp.async.wait_group 1;" ::: "memory")
#define CP_WAIT0()  asm volatile("cp.async.wait_group 0;" ::: "memory")

// ---------------------------------------------------------------------------
// prep: interleaved hi/lo codebook (UNSCALED residual) + norms + zero counts
__global__ void prep_kernel(const float* __restrict__ cb) {
    __shared__ float red[8];
    const int code = blockIdx.x;
    const int c    = threadIdx.x;
    float v = cb[code * C_DIM + c];
    __half hi = __float2half_rn(v);
    __half lo = __float2half_rn(v - __half2float(hi));
    int base = code * 512 + (c >> 3) * 16 + (c & 7);
    g_cbi[base]     = hi;
    g_cbi[base + 8] = lo;
    float s = v * v;
    #pragma unroll
    for (int off = 16; off > 0; off >>= 1)
        s += __shfl_down_sync(0xffffffffu, s, off);
    if ((c & 31) == 0) red[c >> 5] = s;
    __syncthreads();
    if (c == 0) {
        float t = 0.f;
        #pragma unroll
        for (int i = 0; i < 8; i++) t += red[i];
        g_norms[code]  = t;
        g_counts[code] = 0;
    }
}

// ---------------------------------------------------------------------------
// fused split-fp16 GEMM-argmin (+gather +loss).
// 8 warps = 4 token-groups x 2 code-groups; warp tile = 32 tok x 32 codes.
// A-lo fragments persist in registers; single fp32 accumulator for all 3 terms.
__global__ __launch_bounds__(256, 1)
void argmin_fused(const float* __restrict__ z, const float* __restrict__ cb,
                  float* __restrict__ out) {
    extern __shared__ char smem[];
    const uint32_t sb = smem_u32(smem);
    float* ns = (float*)(smem + NS_OFF);

    const int tid  = threadIdx.x;
    const int warp = tid >> 5;
    const int lane = tid & 31;
    const int tg   = warp & 3;       // token group (32 tokens)
    const int cg   = warp >> 2;      // code half of 64-chunk (32 codes)
    const int g    = lane >> 2;
    const int t    = lane & 3;

    const int n0  = blockIdx.x * MT;
    const int b   = n0 >> 10;
    const int hw0 = n0 & 1023;
    const float* zb = z + (size_t)b * (C_DIM * HW_DIM) + hw0;

    // ---- stage A: hi -> AH region, lo -> ring region (temporarily) --------
    for (int it = 0; it < 128; it++) {
        int i  = it * 256 + tid;
        int tk = i & 127;
        int c  = i >> 7;
        float a = zb[(size_t)c * HW_DIM + tk];
        __half hi = __float2half_rn(a);
        __half lo = __float2half_rn(a - __half2float(hi));
        *(__half*)(smem + AH_OFF + tk * AROWB + c * 2)   = hi;
        *(__half*)(smem + RING_OFF + tk * AROWB + c * 2) = lo;
    }
    #pragma unroll
    for (int it = 0; it < 4; it++) ns[it * 256 + tid] = g_norms[it * 256 + tid];
    __syncthreads();

    // ---- preload A-lo fragments into persistent registers -----------------
    uint32_t alo[2][KSTEPS][4];
    {
        const uint32_t aL = sb + RING_OFF
            + (uint32_t)((tg * 32 + (lane & 15)) * AROWB + (lane >> 4) * 16);
        #pragma unroll
        for (int mt = 0; mt < 2; mt++)
            #pragma unroll
            for (int ks = 0; ks < KSTEPS; ks++)
                ldsm4(aL + (uint32_t)(mt * 16 * AROWB + ks * 32), alo[mt][ks]);
    }
    __syncthreads();            // ring region now free for B

    // ---- B prefetch: pair = 64 codes x 1024B rows, XOR-swizzled -----------
    auto prefetch = [&](int p) {
        const char* src = (const char*)g_cbi + (size_t)p * PAIRB;
        uint32_t dst0 = sb + RING_OFF + (uint32_t)((p & 1) * PAIRB);
        #pragma unroll
        for (int it = 0; it < 16; it++) {
            int i    = it * 256 + tid;
            int code = i >> 6;
            int seg  = i & 63;
            uint32_t dst = dst0 + (uint32_t)(code * 1024 + ((seg ^ (code & 7)) << 4));
            CP_ASYNC16(dst, src + (size_t)i * 16);
        }
    };
    prefetch(0); CP_COMMIT();
    prefetch(1); CP_COMMIT();

    const uint32_t aH = sb + AH_OFF
        + (uint32_t)((tg * 32 + (lane & 15)) * AROWB + (lane >> 4) * 16);
    const int bcode = lane & 7;      // row within 8-code tile
    const int bgrp  = lane >> 3;     // which of 4 seg-matrices
    // per-nb row byte base within a pair buffer (cg selects 32-code half)
    uint32_t brow[4];
    #pragma unroll
    for (int nb = 0; nb < 4; nb++)
        brow[nb] = (uint32_t)(cg * 32768 + (nb * 8 + bcode) * 1024);

    float bestv[4];
    int   besti[4];
    #pragma unroll
    for (int s = 0; s < 4; s++) { bestv[s] = 3.4e38f; besti[s] = 0; }

    for (int p = 0; p < PAIRS; p++) {
        if (p == PAIRS - 1) CP_WAIT0(); else CP_WAIT1();
        __syncthreads();

        const uint32_t pbase = sb + RING_OFF + (uint32_t)((p & 1) * PAIRB);

        float acc[2][4][4];
        #pragma unroll
        for (int mt = 0; mt < 2; mt++)
            #pragma unroll
            for (int nb = 0; nb < 4; nb++)
                #pragma unroll
                for (int q = 0; q < 4; q++) acc[mt][nb][q] = 0.f;

        #pragma unroll
        for (int ks = 0; ks < KSTEPS; ks++) {
            uint32_t ahf[2][4];
            #pragma unroll
            for (int mt = 0; mt < 2; mt++)
                ldsm4(aH + (uint32_t)(mt * 16 * AROWB + ks * 32), ahf[mt]);
            #pragma unroll
            for (int nb = 0; nb < 4; nb++) {
                // one ldsm4: [bh k0-7][bl k0-7][bh k8-15][bl k8-15] for 8 codes
                uint32_t bb[4];
                uint32_t baddr = pbase + brow[nb]
                    + (uint32_t)((((4 * ks + bgrp) ^ bcode)) << 4);
                ldsm4(baddr, bb);
                #pragma unroll
                for (int mt = 0; mt < 2; mt++) {
                    mma_f16(acc[mt][nb], ahf[mt],      bb[0], bb[2]);  // ah*bh
                    mma_f16(acc[mt][nb], ahf[mt],      bb[1], bb[3]);  // ah*bl
                    mma_f16(acc[mt][nb], alo[mt][ks],  bb[0], bb[2]);  // al*bh
                }
            }
        }

        __syncthreads();                 // all reads done before refill
        if (p + 2 < PAIRS) { prefetch(p + 2); CP_COMMIT(); }

        // epilogue overlaps async loads: dist = |e|^2 - 2 * dot
        #pragma unroll
        for (int nb = 0; nb < 4; nb++) {
            int cl = cg * 32 + nb * 8 + 2 * t;
            int code0 = p * 64 + cl;
            float nk0 = ns[code0];
            float nk1 = ns[code0 + 1];
            #pragma unroll
            for (int mt = 0; mt < 2; mt++) {
                float d00 = nk0 - 2.f * acc[mt][nb][0];
                float d01 = nk1 - 2.f * acc[mt][nb][1];
                float d10 = nk0 - 2.f * acc[mt][nb][2];
                float d11 = nk1 - 2.f * acc[mt][nb][3];
                int s0 = mt * 2, s1 = mt * 2 + 1;
                if (d00 < bestv[s0]) { bestv[s0] = d00; besti[s0] = code0; }
                if (d01 < bestv[s0]) { bestv[s0] = d01; besti[s0] = code0 + 1; }
                if (d10 < bestv[s1]) { bestv[s1] = d10; besti[s1] = code0; }
                if (d11 < bestv[s1]) { bestv[s1] = d11; besti[s1] = code0 + 1; }
            }
        }
    }

    // lane-reduce across t (lanes 4g..4g+3 share a token row)
    #pragma unroll
    for (int s = 0; s < 4; s++) {
        #pragma unroll
        for (int m = 1; m <= 2; m <<= 1) {
            float v2 = __shfl_xor_sync(0xffffffffu, bestv[s], m);
            int   i2 = __shfl_xor_sync(0xffffffffu, besti[s], m);
            if (v2 < bestv[s] || (v2 == bestv[s] && i2 < besti[s])) {
                bestv[s] = v2; besti[s] = i2;
            }
        }
    }

    // cross-warp merge via smem scratch aliased over the (dead) ring region
    float* candv = (float*)(smem + CV_OFF);
    int*   candi = (int*)(smem + CI_OFF);
    int*   kf    = (int*)(smem + KF_OFF);
    if (t == 0) {
        #pragma unroll
        for (int s = 0; s < 4; s++) {
            int mt = s >> 1, h = s & 1;
            int tok = tg * 32 + mt * 16 + h * 8 + g;
            candv[tok * 2 + cg] = bestv[s];
            candi[tok * 2 + cg] = besti[s];
        }
    }
    __syncthreads();
    if (tid < MT) {
        float v0 = candv[tid * 2], v1 = candv[tid * 2 + 1];
        int   i0 = candi[tid * 2], i1 = candi[tid * 2 + 1];
        int bi;
        if (v1 < v0 || (v1 == v0 && i1 < i0)) bi = i1; else bi = i0;
        kf[tid] = bi;
        atomicAdd(&g_counts[bi], 1);
    }
    __syncthreads();

    // -------- fused gather + loss: 128 tokens x 256 channels ---------------
    {
        const int tok = tid & 127;
        const int ch0 = (tid >> 7) * 128;
        const int k   = kf[tok];
        const float4* crow = (const float4*)(cb + (size_t)k * C_DIM + ch0);
        const float* zp = zb + (size_t)ch0 * HW_DIM + tok;
        float* op = out + (size_t)b * (C_DIM * HW_DIM) + hw0
                        + (size_t)ch0 * HW_DIM + tok;
        float s = 0.f;
        #pragma unroll 8
        for (int j = 0; j < 32; j++) {
            float4 e = crow[j];
            int c = j * 4;
            float d0 = e.x - zp[(c + 0) * HW_DIM];
            float d1 = e.y - zp[(c + 1) * HW_DIM];
            float d2 = e.z - zp[(c + 2) * HW_DIM];
            float d3 = e.w - zp[(c + 3) * HW_DIM];
            s += d0 * d0 + d1 * d1 + d2 * d2 + d3 * d3;
            op[(c + 0) * HW_DIM] = e.x;
            op[(c + 1) * HW_DIM] = e.y;
            op[(c + 2) * HW_DIM] = e.z;
            op[(c + 3) * HW_DIM] = e.w;
        }
        __syncthreads();                 // kf reads done; reuse candv as red
        float* red = candv;
        red[tid] = s;
        __syncthreads();
        for (int off = 128; off > 0; off >>= 1) {
            if (tid < off) red[tid] += red[tid + off];
            __syncthreads();
        }
        if (tid == 0) g_partials[blockIdx.x] = red[0];
    }
}

// ---------------------------------------------------------------------------
__global__ void finalize_kernel(float* __restrict__ out, int out_size) {
    __shared__ float s1[1024];
    __shared__ float s2[1024];
    const int tid = threadIdx.x;
    float ls = (tid < NCTA) ? g_partials[tid] : 0.f;
    float p  = (float)g_counts[tid] * (1.0f / (float)N_TOK);
    float pc = fmaxf(p, 1e-10f);
    s1[tid] = ls;
    s2[tid] = pc * logf(pc);
    __syncthreads();
    for (int off = 512; off > 0; off >>= 1) {
        if (tid < off) { s1[tid] += s1[tid + off]; s2[tid] += s2[tid + off]; }
        __syncthreads();
    }
    if (tid == 0) {
        float mse = s1[0] * (1.0f / (float)Z_ELEMS);
        if (out_size >= Z_ELEMS + 1) out[Z_ELEMS]     = mse * (1.0f + BETA_F);
        if (out_size >= Z_ELEMS + 2) out[Z_ELEMS + 1] = expf(-s2[0]);
    }
}

// ---------------------------------------------------------------------------
extern "C" void kernel_launch(void* const* d_in, const int* in_sizes, int n_in,
                              void* d_out, int out_size) {
    const float* z  = (const float*)d_in[0];
    const float* cb = (const float*)d_in[1];
    float* out = (float*)d_out;

    cudaFuncSetAttribute(argmin_fused,
                         cudaFuncAttributeMaxDynamicSharedMemorySize, SMEM_TOTAL);

    prep_kernel<<<K_CODES, 256>>>(cb);
    argmin_fused<<<NCTA, 256, SMEM_TOTAL>>>(z, cb, out);
    finalize_kernel<<<1, 1024>>>(out, out_size);
}